// round 7
// baseline (speedup 1.0000x reference)
#include <cuda_runtime.h>
#include <cuda.h>
#include <cstdint>

// QRegulariser: out = mean_b( 1 - prod_q cos^2( (hidden@W.T + b)_q / 2 ) )
// B=65536, H=1024, Q=8. HBM-bound: 256 MB of hidden.
//
// R7: per-warp TMA rings. tcgen05 is toolchain-blocked (compute_103 PTX), but
// TMA/mbarrier compiled fine in R6. Replace R4's per-lane LDGSTS with one
// cp.async.bulk.tensor.2d per 4KB chunk (8 rows x 512B): zero LSU/L1 cost for
// the global->smem hop, 16 fewer instr/chunk. Each warp owns a private 3-slot
// ring + mbarriers (no cross-warp sync). RPW=8 (w-LDS amortized to 1.0/128B).

#define HDIM 1024
#define QDIM 8
#define RPW 8
#define WPB 16
#define NTHREADS (WPB * 32)          // 512
#define GRID_SMS 148
#define TOTAL_WARPS (GRID_SMS * WPB) // 2368
#define NCHUNK 8                     // H / 128 elements
#define CHUNK_BYTES (RPW * 512)      // 4096
#define NBUF 3
#define SW_BYTES (QDIM * HDIM * 4)   // 32768
#define DSMEM_BYTES (SW_BYTES + WPB * NBUF * CHUNK_BYTES + 1024)  // 230400

__device__ double g_partials[GRID_SMS];
__device__ unsigned int g_counter = 0;

// ---------- helpers ----------
__device__ __forceinline__ uint32_t smem_u32(const void* p) {
    uint32_t a;
    asm("{ .reg .u64 t; cvta.to.shared.u64 t, %1; cvt.u32.u64 %0, t; }" : "=r"(a) : "l"(p));
    return a;
}
__device__ __forceinline__ uint32_t elect_one() {
    uint32_t p;
    asm volatile("{ .reg .pred p; elect.sync _|p, 0xFFFFFFFF; selp.b32 %0, 1, 0, p; }" : "=r"(p));
    return p;
}
__device__ __forceinline__ uint32_t swz(uint32_t off) {
    return off ^ ((off >> 3) & 0x70u);
}
__device__ __forceinline__ unsigned long long fma2(unsigned long long a,
                                                   unsigned long long b,
                                                   unsigned long long c) {
    unsigned long long d;
    asm("fma.rn.f32x2 %0, %1, %2, %3;" : "=l"(d) : "l"(a), "l"(b), "l"(c));
    return d;
}
__device__ __forceinline__ unsigned long long add2(unsigned long long a,
                                                   unsigned long long b) {
    unsigned long long d;
    asm("add.rn.f32x2 %0, %1, %2;" : "=l"(d) : "l"(a), "l"(b));
    return d;
}
__device__ __forceinline__ unsigned long long packff(float x) {
    unsigned long long d;
    asm("mov.b64 %0, {%1, %1};" : "=l"(d) : "f"(x));
    return d;
}
__device__ __forceinline__ float2 unpack2(unsigned long long v) {
    float2 r;
    asm("mov.b64 {%0, %1}, %2;" : "=f"(r.x), "=f"(r.y) : "l"(v));
    return r;
}
#define MBARRIER_INIT(a, n) \
    asm volatile("mbarrier.init.shared.b64 [%0], %1;" :: "r"(a), "r"((uint32_t)(n)) : "memory")
#define MBARRIER_EXPECT_TX(a, tx) \
    asm volatile("mbarrier.arrive.expect_tx.shared.b64 _, [%0], %1;" :: "r"(a), "r"((uint32_t)(tx)) : "memory")
#define MBAR_WAIT(a, par) do {                                              \
    uint32_t _m = (a), _p = (par), _d;                                      \
    asm volatile("{ .reg .pred p; mbarrier.try_wait.parity.acquire.cta.shared::cta.b64 p, [%1], %2;" \
                 " selp.b32 %0, 1, 0, p; }" : "=r"(_d) : "r"(_m), "r"(_p) : "memory");             \
    if (!_d) {                                                              \
        asm volatile("{ .reg .pred P1; WL_%=: mbarrier.try_wait.parity.acquire.cta.shared::cta.b64 P1, [%0], %1, 0x989680;" \
                     " @P1 bra.uni WD_%=; bra.uni WL_%=; WD_%=: }" :: "r"(_m), "r"(_p) : "memory"); \
    } } while (0)
__device__ __forceinline__ void tma_load_2d(uint32_t dst, const void* map,
                                            int x, int y, uint32_t mbar) {
    asm volatile("cp.async.bulk.tensor.2d.shared::cta.global.tile.mbarrier::complete_tx::bytes "
                 "[%0], [%1, {%2, %3}], [%4];"
                 :: "r"(dst), "l"(map), "r"(x), "r"(y), "r"(mbar) : "memory");
}

// ---------- kernel ----------
__global__ __launch_bounds__(NTHREADS, 1)
void qreg_tma_kernel(const __grid_constant__ CUtensorMap tmap,
                     const float* __restrict__ Wm,
                     const float* __restrict__ bv,
                     float* __restrict__ out,
                     int B) {
    extern __shared__ char dsm_raw[];
    __shared__ __align__(8) uint64_t mb[WPB * NBUF];
    __shared__ float sB[QDIM];
    __shared__ double warp_sums[WPB];
    __shared__ unsigned int is_last;

    const int tid = threadIdx.x;
    const int warp = tid >> 5, lane = tid & 31;
    const int bid = blockIdx.x;

    // 128-align the dynamic region.
    const uint32_t raw = smem_u32(dsm_raw);
    const uint32_t base = (raw + 127u) & ~127u;
    char* sWg = dsm_raw + (base - raw);
    const uint32_t stage0 = base + SW_BYTES;

    // Build swizzled W^T: column c gets 32B (q0..q7) at off = c*32 + q*4.
    for (int i = tid; i < QDIM * HDIM / 4; i += NTHREADS) {
        const float4 v = reinterpret_cast<const float4*>(Wm)[i];
        const int q = (i * 4) / HDIM;
        const int c = (i * 4) % HDIM;
        const float vv[4] = {v.x, v.y, v.z, v.w};
        #pragma unroll
        for (int j = 0; j < 4; ++j) {
            const uint32_t off = swz((uint32_t)(c + j) * 32u + (uint32_t)q * 4u);
            *reinterpret_cast<float*>(sWg + off) = vv[j];
        }
    }
    if (tid < QDIM) sB[tid] = bv[tid];

    // Each warp initializes its own ring barriers (arrive count 1: the TMA tx).
    if (elect_one()) {
        #pragma unroll
        for (int s = 0; s < NBUF; ++s)
            MBARRIER_INIT(smem_u32(&mb[warp * NBUF + s]), 1);
    }
    __syncthreads();

    const int gw = bid * WPB + warp;            // global warp id
    const int ntasks = (B + RPW - 1) / RPW;     // row-groups of 8
    int nmy = 0;
    if (gw < ntasks) nmy = (ntasks - 1 - gw) / TOTAL_WARPS + 1;
    const int nchunks = nmy * NCHUNK;

    const uint32_t mybuf = stage0 + (uint32_t)warp * (NBUF * CHUNK_BYTES);
    char* mybuf_g = dsm_raw + (mybuf - raw);
    const uint32_t mymb0 = smem_u32(&mb[warp * NBUF]);

    double local = 0.0;

    if (nchunks > 0) {
        // Issue TMA for global chunk g into ring slot g%NBUF (elected lane).
        auto issue = [&](int g) {
            const int k = g >> 3, it = g & 7;
            const int row0 = (gw + k * TOTAL_WARPS) * RPW;
            const int s = g % NBUF;
            MBARRIER_EXPECT_TX(mymb0 + s * 8, CHUNK_BYTES);
            tma_load_2d(mybuf + s * CHUNK_BYTES, &tmap, it * 128, row0, mymb0 + s * 8);
        };

        if (elect_one()) {
            issue(0);
            if (nchunks > 1) issue(1);
        }

        unsigned long long acc[RPW][4];
        #pragma unroll
        for (int r = 0; r < RPW; ++r)
            #pragma unroll
            for (int qp = 0; qp < 4; ++qp) acc[r][qp] = 0ull;

        for (int g = 0; g < nchunks; ++g) {
            const int s = g % NBUF;
            const uint32_t par = (uint32_t)((g / NBUF) & 1);
            MBAR_WAIT(mymb0 + s * 8, par);

            const char* buf = mybuf_g + s * CHUNK_BYTES;
            float4 h[RPW];
            #pragma unroll
            for (int r = 0; r < RPW; ++r)
                h[r] = *reinterpret_cast<const float4*>(buf + r * 512 + lane * 16);

            const int it = g & 7;
            const int col4 = it * 32 + lane;
            #pragma unroll
            for (int j = 0; j < 4; ++j) {
                const uint32_t wb = (uint32_t)col4 * 128u + (uint32_t)j * 32u;
                const ulonglong2 wA = *reinterpret_cast<const ulonglong2*>(sWg + swz(wb));
                const ulonglong2 wB = *reinterpret_cast<const ulonglong2*>(sWg + swz(wb + 16u));
                #pragma unroll
                for (int r = 0; r < RPW; ++r) {
                    const float* hp = &h[r].x;
                    const unsigned long long hh = packff(hp[j]);
                    acc[r][0] = fma2(hh, wA.x, acc[r][0]);
                    acc[r][1] = fma2(hh, wA.y, acc[r][1]);
                    acc[r][2] = fma2(hh, wB.x, acc[r][2]);
                    acc[r][3] = fma2(hh, wB.y, acc[r][3]);
                }
            }

            // Reissue this pipeline depth AFTER the fmas consumed slot g
            // (warp-wide scoreboard: all lanes' LDS of slot (g+2)%NBUF's
            // previous round retired before this point).
            if (g + 2 < nchunks && elect_one()) issue(g + 2);

            if (it == NCHUNK - 1) {
                // Row-group complete: butterfly-reduce, epilogue.
                #pragma unroll
                for (int r = 0; r < RPW; ++r) {
                    #pragma unroll
                    for (int qp = 0; qp < 4; ++qp) {
                        unsigned long long v = acc[r][qp];
                        #pragma unroll
                        for (int d = 16; d > 0; d >>= 1)
                            v = add2(v, __shfl_xor_sync(0xffffffffu, v, d));
                        acc[r][qp] = v;
                    }
                }
                const int row0 = (gw + (g >> 3) * TOTAL_WARPS) * RPW;
                #pragma unroll
                for (int r = 0; r < RPW; ++r) {
                    if (row0 + r >= B) continue;
                    float pr = 1.0f;
                    #pragma unroll
                    for (int qp = 0; qp < 4; ++qp) {
                        const float2 th = unpack2(acc[r][qp]);
                        const float t0 = th.x + sB[2 * qp];
                        const float t1 = th.y + sB[2 * qp + 1];
                        pr *= 0.25f * (1.0f + __cosf(t0)) * (1.0f + __cosf(t1));
                    }
                    local += (double)(1.0f - pr);
                }
                #pragma unroll
                for (int r = 0; r < RPW; ++r)
                    #pragma unroll
                    for (int qp = 0; qp < 4; ++qp) acc[r][qp] = 0ull;
            }
        }
    }

    if (lane == 0) warp_sums[warp] = local;
    __syncthreads();

    if (tid == 0) {
        double s = 0.0;
        #pragma unroll
        for (int w = 0; w < WPB; ++w) s += warp_sums[w];
        g_partials[bid] = s;
        __threadfence();
        const unsigned int prev = atomicAdd(&g_counter, 1u);
        is_last = (prev == gridDim.x - 1) ? 1u : 0u;
    }
    __syncthreads();

    if (is_last) {
        __threadfence();
        const volatile double* vp = g_partials;
        double s = 0.0;
        for (int i = tid; i < (int)gridDim.x; i += NTHREADS) s += vp[i];
        #pragma unroll
        for (int d = 16; d > 0; d >>= 1)
            s += __shfl_down_sync(0xffffffffu, s, d);
        if (lane == 0) warp_sums[warp] = s;
        __syncthreads();
        if (tid == 0) {
            double t = 0.0;
            #pragma unroll
            for (int w = 0; w < WPB; ++w) t += warp_sums[w];
            out[0] = (float)(t / (double)B);
            g_counter = 0;   // reset for graph replay
        }
    }
}

// ---------- host ----------
typedef CUresult (*EncodeTiledFn)(CUtensorMap*, CUtensorMapDataType, cuuint32_t, void*,
                                  const cuuint64_t*, const cuuint64_t*,
                                  const cuuint32_t*, const cuuint32_t*,
                                  CUtensorMapInterleave, CUtensorMapSwizzle,
                                  CUtensorMapL2promotion, CUtensorMapFloatOOBfill);

extern "C" void kernel_launch(void* const* d_in, const int* in_sizes, int n_in,
                              void* d_out, int out_size) {
    const float* hidden = (const float*)d_in[0];   // [B, H] f32
    const float* Wm     = (const float*)d_in[1];   // [Q, H] f32
    const float* bv     = (const float*)d_in[2];   // [Q]    f32
    float* out = (float*)d_out;

    const int B = in_sizes[0] / HDIM;

    void* fp = nullptr;
    cudaDriverEntryPointQueryResult qr;
    cudaGetDriverEntryPoint("cuTensorMapEncodeTiled", &fp, cudaEnableDefault, &qr);
    EncodeTiledFn encode = (EncodeTiledFn)fp;

    CUtensorMap tmap;
    cuuint64_t dims[2]    = {(cuuint64_t)HDIM, (cuuint64_t)B};
    cuuint64_t strides[1] = {(cuuint64_t)HDIM * 4};
    cuuint32_t box[2]     = {128, RPW};           // 512 B x 8 rows = 4 KB
    cuuint32_t estr[2]    = {1, 1};
    encode(&tmap, CU_TENSOR_MAP_DATA_TYPE_FLOAT32, 2, (void*)hidden,
           dims, strides, box, estr,
           CU_TENSOR_MAP_INTERLEAVE_NONE, CU_TENSOR_MAP_SWIZZLE_NONE,
           CU_TENSOR_MAP_L2_PROMOTION_L2_128B, CU_TENSOR_MAP_FLOAT_OOB_FILL_NONE);

    static bool attr_set = false;
    if (!attr_set) {
        cudaFuncSetAttribute(qreg_tma_kernel,
                             cudaFuncAttributeMaxDynamicSharedMemorySize,
                             DSMEM_BYTES);
        attr_set = true;
    }

    qreg_tma_kernel<<<GRID_SMS, NTHREADS, DSMEM_BYTES>>>(tmap, Wm, bv, out, B);
}

// round 8
// speedup vs baseline: 1.4300x; 1.4300x over previous
#include <cuda_runtime.h>
#include <cstdint>

// QRegulariser: out = mean_b( 1 - prod_q cos^2( (hidden@W.T + b)_q / 2 ) )
// B=65536, H=1024, Q=8. HBM-bound: 256 MB of hidden.
//
// R8: compute moved to HMMA (mma.sync.m16n8k8.tf32; tcgen05 is blocked by the
// compute_103 PTX target but classic mma.sync is sm_80 PTX). Data path = R4's
// per-warp LDGSTS ring (best measured). SIMT FMA cost ~0.05 instr/B was the
// structural ceiling (~5TB/s); HMMA cuts instr/byte ~3x.
//  - warp task = 16 rows x K=1024, one m16n8k8 MMA per 8-k slice, N=8.
//  - A staged 2KB/chunk (16 rows x 32k), XOR-quad swizzle, conflict-free LDS.32.
//  - B (W) pre-packed fragments in smem: 1 LDS.64 per MMA.
//  - 32 warps/CTA, 148 CTAs, warp-interleaved tasks: 4096 tasks, <=28/SM.

#define HDIM 1024
#define QDIM 8
#define MPW 16                         // rows per warp task (MMA M)
#define WPB 32
#define NTHREADS (WPB * 32)            // 1024
#define GRID_SMS 148
#define TOTAL_WARPS (GRID_SMS * WPB)   // 4736
#define KCHUNK 32
#define NCHUNKS (HDIM / KCHUNK)        // 32
#define CHUNK_BYTES (MPW * KCHUNK * 4) // 2048
#define NBUF 2
#define NSLICES (HDIM / 8)             // 128 B-fragment slices
#define BFRAG_BYTES (NSLICES * 32 * 8) // 32768
#define ASTAGE_BYTES (WPB * NBUF * CHUNK_BYTES) // 131072
#define DSMEM_BYTES (BFRAG_BYTES + ASTAGE_BYTES + 256)

__device__ double g_partials[GRID_SMS];
__device__ unsigned int g_counter = 0;

__device__ __forceinline__ uint32_t smem_u32(const void* p) {
    uint32_t a;
    asm("{ .reg .u64 t; cvta.to.shared.u64 t, %1; cvt.u32.u64 %0, t; }" : "=r"(a) : "l"(p));
    return a;
}
__device__ __forceinline__ void cp16(uint32_t dst, const void* src) {
    asm volatile("cp.async.cg.shared.global [%0], [%1], 16;"
                 :: "r"(dst), "l"(src) : "memory");
}
__device__ __forceinline__ void sts_zero16(uint32_t dst) {
    asm volatile("st.shared.v4.u32 [%0], {%1, %1, %1, %1};"
                 :: "r"(dst), "r"(0u) : "memory");
}
__device__ __forceinline__ void cp_commit() {
    asm volatile("cp.async.commit_group;" ::: "memory");
}
__device__ __forceinline__ void cp_wait1() {
    asm volatile("cp.async.wait_group 1;" ::: "memory");
}
__device__ __forceinline__ void cp_wait0() {
    asm volatile("cp.async.wait_group 0;" ::: "memory");
}
// D(16x8) += A(16x8) * B(8x8); tf32 inputs as raw f32 bit patterns.
__device__ __forceinline__ void mma_tf32(float4& d,
                                         uint32_t a0, uint32_t a1, uint32_t a2, uint32_t a3,
                                         uint32_t b0, uint32_t b1) {
    asm volatile(
        "mma.sync.aligned.m16n8k8.row.col.f32.tf32.tf32.f32 "
        "{%0,%1,%2,%3}, {%4,%5,%6,%7}, {%8,%9}, {%0,%1,%2,%3};"
        : "+f"(d.x), "+f"(d.y), "+f"(d.z), "+f"(d.w)
        : "r"(a0), "r"(a1), "r"(a2), "r"(a3), "r"(b0), "r"(b1));
}

__global__ __launch_bounds__(NTHREADS, 1)
void qreg_hmma_kernel(const float* __restrict__ hidden,
                      const float* __restrict__ Wm,
                      const float* __restrict__ bv,
                      float* __restrict__ out,
                      int B) {
    extern __shared__ char dsm_raw[];
    __shared__ double warp_sums[WPB];
    __shared__ unsigned int is_last;

    const int tid = threadIdx.x;
    const int warp = tid >> 5, lane = tid & 31;
    const int bid = blockIdx.x;

    // 128-align dynamic smem.
    const uint32_t raw = smem_u32(dsm_raw);
    const uint32_t base = (raw + 127u) & ~127u;
    char* sBf = dsm_raw + (base - raw);            // 32 KB B fragments
    const uint32_t astage0 = base + BFRAG_BYTES;   // A staging
    char* astage0_g = sBf + BFRAG_BYTES;

    // Pack B fragments: slice s covers k in [8s, 8s+8).
    // m16n8k8 tf32 B mapping: b0 = B[k = l%4,   n = l/4] = W[n][8s + l%4]
    //                         b1 = B[k = l%4+4, n = l/4] = W[n][8s + l%4 + 4]
    for (int i = tid; i < NSLICES * 32; i += NTHREADS) {
        const int s = i >> 5, l = i & 31;
        const int n = l >> 2, k = 8 * s + (l & 3);
        float2 v;
        v.x = Wm[n * HDIM + k];
        v.y = Wm[n * HDIM + k + 4];
        *reinterpret_cast<float2*>(sBf + s * 256 + l * 8) = v;
    }
    __syncthreads();

    // Warp-interleaved task assignment spreads active warps across SMs.
    const int gw = warp * GRID_SMS + bid;
    const int ngroups = (B + MPW - 1) / MPW;       // 4096 for B=65536

    const uint32_t mybuf = astage0 + (uint32_t)warp * (NBUF * CHUNK_BYTES);
    char* mybuf_g = astage0_g + warp * (NBUF * CHUNK_BYTES);

    const int rl = lane >> 2;                       // fragment row 0..7
    const int kl = lane & 3;                        // fragment k lane 0..3
    const float b0v = bv[2 * kl];
    const float b1v = bv[2 * kl + 1];

    double local = 0.0;

    for (int grp = gw; grp < ngroups; grp += TOTAL_WARPS) {
        const int row0 = grp * MPW;
        const bool guard = (row0 + MPW > B);

        // Issue LDGSTS for chunk c into ring slot c&1.
        // Granule g = p*32+lane: row r = g/8 (16 rows), col quad c4 = g%8.
        // Swizzle: quad' = c4 ^ (r&7) -> conflict-free STS and LDS.
        auto issue = [&](int c) {
            const uint32_t dst0 = mybuf + (uint32_t)(c & 1) * CHUNK_BYTES;
            #pragma unroll
            for (int p = 0; p < 4; ++p) {
                const int g = p * 32 + lane;
                const int r = g >> 3, c4 = g & 7;
                const uint32_t dst = dst0 + (uint32_t)r * 128u
                                   + (uint32_t)((c4 ^ (r & 7)) << 4);
                if (!guard || (row0 + r) < B)
                    cp16(dst, (const char*)hidden
                              + (size_t)(row0 + r) * (HDIM * 4)
                              + (size_t)c * 128 + (size_t)c4 * 16);
                else
                    sts_zero16(dst);
            }
            cp_commit();
        };

        issue(0);
        issue(1);

        float4 acc0 = make_float4(0.f, 0.f, 0.f, 0.f);  // slices j = 0,2
        float4 acc1 = make_float4(0.f, 0.f, 0.f, 0.f);  // slices j = 1,3

        for (int c = 0; c < NCHUNKS; ++c) {
            cp_wait1();                                 // chunk c resident

            const char* buf = mybuf_g + (c & 1) * CHUNK_BYTES;
            // Lane base inside its fragment rows (rl and rl+8).
            const char* arow = buf + rl * 128 + kl * 4;

            // Load all A fragments for the 4 slices (LDS.32, conflict-free),
            // then reissue the pipeline, then run the MMAs.
            uint32_t a[4][4];
            float2 bf[4];
            #pragma unroll
            for (int j = 0; j < 4; ++j) {
                const int q0 = ((2 * j) ^ rl) << 4;
                const int q1 = ((2 * j + 1) ^ rl) << 4;
                a[j][0] = *reinterpret_cast<const uint32_t*>(arow + q0);
                a[j][1] = *reinterpret_cast<const uint32_t*>(arow + 1024 + q0);
                a[j][2] = *reinterpret_cast<const uint32_t*>(arow + q1);
                a[j][3] = *reinterpret_cast<const uint32_t*>(arow + 1024 + q1);
                bf[j] = *reinterpret_cast<const float2*>(
                            sBf + (size_t)(c * 4 + j) * 256 + lane * 8);
            }

            if (c + 2 < NCHUNKS) issue(c + 2);  // after A reads of this slot

            #pragma unroll
            for (int j = 0; j < 4; ++j) {
                float4& acc = (j & 1) ? acc1 : acc0;
                mma_tf32(acc, a[j][0], a[j][1], a[j][2], a[j][3],
                         __float_as_uint(bf[j].x), __float_as_uint(bf[j].y));
            }
        }
        cp_wait0();   // drain before next group reuses the ring

        // theta: row rA = row0+rl (c0,c1), row rB = rA+8 (c2,c3),
        // cols 2*kl and 2*kl+1.
        const float tA0 = acc0.x + acc1.x + b0v;
        const float tA1 = acc0.y + acc1.y + b1v;
        const float tB0 = acc0.z + acc1.z + b0v;
        const float tB1 = acc0.w + acc1.w + b1v;

        // Per-lane partial product over its 2 q's; multiply across the quad
        // (lanes 4rl..4rl+3 hold q-pairs {0,1},{2,3},{4,5},{6,7}).
        float pA = 0.25f * (1.0f + __cosf(tA0)) * (1.0f + __cosf(tA1));
        float pB = 0.25f * (1.0f + __cosf(tB0)) * (1.0f + __cosf(tB1));
        #pragma unroll
        for (int d = 1; d <= 2; d <<= 1) {
            pA *= __shfl_xor_sync(0xffffffffu, pA, d);
            pB *= __shfl_xor_sync(0xffffffffu, pB, d);
        }

        const int rowA = row0 + rl, rowB = rowA + 8;
        float s = ((!guard || rowA < B) ? (1.0f - pA) : 0.0f)
                + ((!guard || rowB < B) ? (1.0f - pB) : 0.0f);
        // Each quad's s is replicated in 4 lanes; full butterfly sums 4x.
        #pragma unroll
        for (int d = 1; d <= 16; d <<= 1)
            s += __shfl_xor_sync(0xffffffffu, s, d);
        local += (double)s * 0.25;
    }

    if (lane == 0) warp_sums[warp] = local;
    __syncthreads();

    if (tid == 0) {
        double ssum = 0.0;
        #pragma unroll
        for (int w = 0; w < WPB; ++w) ssum += warp_sums[w];
        g_partials[bid] = ssum;
        __threadfence();
        const unsigned int prev = atomicAdd(&g_counter, 1u);
        is_last = (prev == gridDim.x - 1) ? 1u : 0u;
    }
    __syncthreads();

    if (is_last) {
        __threadfence();
        const volatile double* vp = g_partials;
        double ssum = 0.0;
        for (int i = tid; i < (int)gridDim.x; i += NTHREADS) ssum += vp[i];
        #pragma unroll
        for (int d = 16; d > 0; d >>= 1)
            ssum += __shfl_down_sync(0xffffffffu, ssum, d);
        if (lane == 0) warp_sums[warp] = ssum;
        __syncthreads();
        if (tid == 0) {
            double t = 0.0;
            #pragma unroll
            for (int w = 0; w < WPB; ++w) t += warp_sums[w];
            out[0] = (float)(t / (double)B);
            g_counter = 0;   // reset for graph replay
        }
    }
}

extern "C" void kernel_launch(void* const* d_in, const int* in_sizes, int n_in,
                              void* d_out, int out_size) {
    const float* hidden = (const float*)d_in[0];   // [B, H] f32
    const float* Wm     = (const float*)d_in[1];   // [Q, H] f32
    const float* bv     = (const float*)d_in[2];   // [Q]    f32
    float* out = (float*)d_out;

    const int B = in_sizes[0] / HDIM;

    static bool attr_set = false;
    if (!attr_set) {
        cudaFuncSetAttribute(qreg_hmma_kernel,
                             cudaFuncAttributeMaxDynamicSharedMemorySize,
                             DSMEM_BYTES);
        attr_set = true;
    }

    qreg_hmma_kernel<<<GRID_SMS, NTHREADS, DSMEM_BYTES>>>(hidden, Wm, bv, out, B);
}

// round 9
// speedup vs baseline: 1.5795x; 1.1045x over previous
#include <cuda_runtime.h>
#include <cuda.h>
#include <cstdint>

// QRegulariser: out = mean_b( 1 - prod_q cos^2( (hidden@W.T + b)_q / 2 ) )
// B=65536, H=1024, Q=8. HBM-bound: 256 MB of hidden.
//
// R9: CTA-level TMA producer/consumer. R3/R4/R8 all pinned DRAM at 60-64%
// regardless of instruction profile -> the common limiter is the LSU/L1tex
// request path. TMA bulk loads bypass it entirely (LTS-cap path-independent).
//  - producer warp: 8KB stages (64 rows x 128B, SW128) into a 16-deep ring,
//    mbarrier expect_tx handshake (pattern validated in R7).
//  - 4 consumer warps: 16-row slice each, R8's m16n8k8 tf32 MMA + epilogue.
//  - tile = 64 rows: 1024 tiles / 148 SMs = 6.92 -> ~1% tail.

#define HDIM 1024
#define QDIM 8
#define TILE_ROWS 64
#define KCHUNK 32                       // k-elements per stage (128 B/row)
#define NSPT (HDIM / KCHUNK)            // 32 stages per tile
#define STAGE_BYTES (TILE_ROWS * KCHUNK * 4)   // 8192
#define NSTAGE 16
#define NCONS 4                          // consumer warps
#define NTHREADS 160                     // 4 consumers + 1 producer
#define GRID_SMS 148
#define NSLICES (HDIM / 8)               // 128 B-fragment slices
#define BFRAG_BYTES (NSLICES * 32 * 8)   // 32768
#define DSMEM_BYTES (BFRAG_BYTES + NSTAGE * STAGE_BYTES + 1024)  // ~164 KB

__device__ double g_partials[GRID_SMS];
__device__ unsigned int g_counter = 0;

__device__ __forceinline__ uint32_t smem_u32(const void* p) {
    uint32_t a;
    asm("{ .reg .u64 t; cvta.to.shared.u64 t, %1; cvt.u32.u64 %0, t; }" : "=r"(a) : "l"(p));
    return a;
}
__device__ __forceinline__ uint32_t elect_one() {
    uint32_t p;
    asm volatile("{ .reg .pred p; elect.sync _|p, 0xFFFFFFFF; selp.b32 %0, 1, 0, p; }" : "=r"(p));
    return p;
}
#define MBARRIER_INIT(a, n) \
    asm volatile("mbarrier.init.shared.b64 [%0], %1;" :: "r"(a), "r"((uint32_t)(n)) : "memory")
#define MBARRIER_EXPECT_TX(a, tx) \
    asm volatile("mbarrier.arrive.expect_tx.shared.b64 _, [%0], %1;" :: "r"(a), "r"((uint32_t)(tx)) : "memory")
#define MBARRIER_ARRIVE(a) \
    asm volatile("mbarrier.arrive.shared.b64 _, [%0];" :: "r"(a) : "memory")
#define MBAR_WAIT(a, par) do {                                              \
    uint32_t _m = (a), _p = (par), _d;                                      \
    asm volatile("{ .reg .pred p; mbarrier.try_wait.parity.acquire.cta.shared::cta.b64 p, [%1], %2;" \
                 " selp.b32 %0, 1, 0, p; }" : "=r"(_d) : "r"(_m), "r"(_p) : "memory");             \
    if (!_d) {                                                              \
        asm volatile("{ .reg .pred P1; WL_%=: mbarrier.try_wait.parity.acquire.cta.shared::cta.b64 P1, [%0], %1, 0x989680;" \
                     " @P1 bra.uni WD_%=; bra.uni WL_%=; WD_%=: }" :: "r"(_m), "r"(_p) : "memory"); \
    } } while (0)
__device__ __forceinline__ void tma_load_2d(uint32_t dst, const void* map,
                                            int x, int y, uint32_t mbar) {
    asm volatile("cp.async.bulk.tensor.2d.shared::cta.global.tile.mbarrier::complete_tx::bytes "
                 "[%0], [%1, {%2, %3}], [%4];"
                 :: "r"(dst), "l"(map), "r"(x), "r"(y), "r"(mbar) : "memory");
}
// D(16x8) += A(16x8) * B(8x8); tf32 inputs as raw f32 bit patterns.
__device__ __forceinline__ void mma_tf32(float4& d,
                                         uint32_t a0, uint32_t a1, uint32_t a2, uint32_t a3,
                                         uint32_t b0, uint32_t b1) {
    asm volatile(
        "mma.sync.aligned.m16n8k8.row.col.f32.tf32.tf32.f32 "
        "{%0,%1,%2,%3}, {%4,%5,%6,%7}, {%8,%9}, {%0,%1,%2,%3};"
        : "+f"(d.x), "+f"(d.y), "+f"(d.z), "+f"(d.w)
        : "r"(a0), "r"(a1), "r"(a2), "r"(a3), "r"(b0), "r"(b1));
}

__global__ __launch_bounds__(NTHREADS, 1)
void qreg_tmapipe_kernel(const __grid_constant__ CUtensorMap tmap,
                         const float* __restrict__ Wm,
                         const float* __restrict__ bv,
                         float* __restrict__ out,
                         int B) {
    extern __shared__ char dsm_raw[];
    __shared__ __align__(8) uint64_t mb_full[NSTAGE], mb_empty[NSTAGE];
    __shared__ double warp_sums[NCONS];
    __shared__ unsigned int is_last;

    const int tid = threadIdx.x;
    const int warp = tid >> 5, lane = tid & 31;
    const int bid = blockIdx.x;

    // 1024-align dynamic smem (SW128 tiles need 1024 alignment).
    const uint32_t raw = smem_u32(dsm_raw);
    const uint32_t base = (raw + 1023u) & ~1023u;
    char* sBf = dsm_raw + (base - raw);            // 32 KB B fragments
    const uint32_t stage0 = base + BFRAG_BYTES;    // staging ring
    char* stage0_g = sBf + BFRAG_BYTES;

    // Pack B fragments (same mapping as R8, validated):
    // slice s covers k in [8s,8s+8): lane l -> (b0,b1) = W[l/4][8s+l%4], W[l/4][8s+l%4+4]
    for (int i = tid; i < NSLICES * 32; i += NTHREADS) {
        const int s = i >> 5, l = i & 31;
        const int n = l >> 2, k = 8 * s + (l & 3);
        float2 v;
        v.x = Wm[n * HDIM + k];
        v.y = Wm[n * HDIM + k + 4];
        *reinterpret_cast<float2*>(sBf + s * 256 + l * 8) = v;
    }
    if (tid == 0) {
        #pragma unroll
        for (int s = 0; s < NSTAGE; ++s) {
            MBARRIER_INIT(smem_u32(&mb_full[s]), 1);      // TMA tx completes it
            MBARRIER_INIT(smem_u32(&mb_empty[s]), NCONS); // 1 arrive per consumer
        }
    }
    __syncthreads();

    const int ntiles = (B + TILE_ROWS - 1) / TILE_ROWS;

    if (warp == NCONS) {
        // ---- Producer: single elected thread streams all stages.
        if (elect_one()) {
            int g = 0;
            for (int t = bid; t < ntiles; t += GRID_SMS) {
                const int row0 = t * TILE_ROWS;
                for (int s = 0; s < NSPT; ++s, ++g) {
                    const int slot = g & (NSTAGE - 1);
                    const uint32_t par = (((g >> 4) & 1) ^ 1);  // first pass free
                    MBAR_WAIT(smem_u32(&mb_empty[slot]), par);
                    MBARRIER_EXPECT_TX(smem_u32(&mb_full[slot]), STAGE_BYTES);
                    tma_load_2d(stage0 + slot * STAGE_BYTES, &tmap,
                                s * KCHUNK, row0, smem_u32(&mb_full[slot]));
                }
            }
        }
    } else {
        // ---- Consumer warp w: rows [w*16, w*16+16) of each 64-row tile.
        const int rl = lane >> 2;            // fragment row 0..7
        const int kl = lane & 3;             // fragment k-lane 0..3
        const float b0v = bv[2 * kl];
        const float b1v = bv[2 * kl + 1];
        const int rA = warp * 16 + rl;       // stage-local rows (rB = rA + 8)
        // SW128 within a row r: inner offset XORed by (r&7)<<4. rA,rA+8 share r&7==rl.
        const char* laneA = stage0_g + rA * 128 + kl * 4;

        double local = 0.0;
        int g = 0;
        for (int t = bid; t < ntiles; t += GRID_SMS) {
            const int row0 = t * TILE_ROWS;
            float4 acc0 = make_float4(0.f, 0.f, 0.f, 0.f);
            float4 acc1 = make_float4(0.f, 0.f, 0.f, 0.f);

            for (int s = 0; s < NSPT; ++s, ++g) {
                const int slot = g & (NSTAGE - 1);
                const uint32_t par = (g >> 4) & 1;
                MBAR_WAIT(smem_u32(&mb_full[slot]), par);

                const char* a0p = laneA + slot * STAGE_BYTES;
                uint32_t a[4][4];
                float2 bf[4];
                #pragma unroll
                for (int j = 0; j < 4; ++j) {
                    const int q0 = ((2 * j) ^ rl) << 4;
                    const int q1 = ((2 * j + 1) ^ rl) << 4;
                    a[j][0] = *reinterpret_cast<const uint32_t*>(a0p + q0);
                    a[j][1] = *reinterpret_cast<const uint32_t*>(a0p + 1024 + q0);
                    a[j][2] = *reinterpret_cast<const uint32_t*>(a0p + q1);
                    a[j][3] = *reinterpret_cast<const uint32_t*>(a0p + 1024 + q1);
                    bf[j] = *reinterpret_cast<const float2*>(
                                sBf + (size_t)(s * 4 + j) * 256 + lane * 8);
                }
                // Reads done -> free the slot (release orders prior LDS).
                if (elect_one()) MBARRIER_ARRIVE(smem_u32(&mb_empty[slot]));

                #pragma unroll
                for (int j = 0; j < 4; ++j) {
                    float4& acc = (j & 1) ? acc1 : acc0;
                    mma_tf32(acc, a[j][0], a[j][1], a[j][2], a[j][3],
                             __float_as_uint(bf[j].x), __float_as_uint(bf[j].y));
                }
            }

            // Tile epilogue (identical math to R8).
            const float tA0 = acc0.x + acc1.x + b0v;
            const float tA1 = acc0.y + acc1.y + b1v;
            const float tB0 = acc0.z + acc1.z + b0v;
            const float tB1 = acc0.w + acc1.w + b1v;
            float pA = 0.25f * (1.0f + __cosf(tA0)) * (1.0f + __cosf(tA1));
            float pB = 0.25f * (1.0f + __cosf(tB0)) * (1.0f + __cosf(tB1));
            #pragma unroll
            for (int d = 1; d <= 2; d <<= 1) {
                pA *= __shfl_xor_sync(0xffffffffu, pA, d);
                pB *= __shfl_xor_sync(0xffffffffu, pB, d);
            }
            const int rowA = row0 + warp * 16 + rl;
            const int rowB = rowA + 8;
            float sv = ((rowA < B) ? (1.0f - pA) : 0.0f)
                     + ((rowB < B) ? (1.0f - pB) : 0.0f);
            #pragma unroll
            for (int d = 1; d <= 16; d <<= 1)
                sv += __shfl_xor_sync(0xffffffffu, sv, d);
            local += (double)sv * 0.25;   // quad replication
        }
        if (lane == 0) warp_sums[warp] = local;
    }
    __syncthreads();

    if (tid == 0) {
        double ssum = 0.0;
        #pragma unroll
        for (int w = 0; w < NCONS; ++w) ssum += warp_sums[w];
        g_partials[bid] = ssum;
        __threadfence();
        const unsigned int prev = atomicAdd(&g_counter, 1u);
        is_last = (prev == gridDim.x - 1) ? 1u : 0u;
    }
    __syncthreads();

    if (is_last) {
        __threadfence();
        const volatile double* vp = g_partials;
        double ssum = 0.0;
        for (int i = tid; i < (int)gridDim.x; i += NTHREADS) ssum += vp[i];
        #pragma unroll
        for (int d = 16; d > 0; d >>= 1)
            ssum += __shfl_down_sync(0xffffffffu, ssum, d);
        __shared__ double fin[5];
        if (lane == 0) fin[warp] = ssum;
        __syncthreads();
        if (tid == 0) {
            double t = 0.0;
            #pragma unroll
            for (int w = 0; w < 5; ++w) t += fin[w];
            out[0] = (float)(t / (double)B);
            g_counter = 0;   // reset for graph replay
        }
    }
}

// ---------- host ----------
typedef CUresult (*EncodeTiledFn)(CUtensorMap*, CUtensorMapDataType, cuuint32_t, void*,
                                  const cuuint64_t*, const cuuint64_t*,
                                  const cuuint32_t*, const cuuint32_t*,
                                  CUtensorMapInterleave, CUtensorMapSwizzle,
                                  CUtensorMapL2promotion, CUtensorMapFloatOOBfill);

extern "C" void kernel_launch(void* const* d_in, const int* in_sizes, int n_in,
                              void* d_out, int out_size) {
    const float* hidden = (const float*)d_in[0];   // [B, H] f32
    const float* Wm     = (const float*)d_in[1];   // [Q, H] f32
    const float* bv     = (const float*)d_in[2];   // [Q]    f32
    float* out = (float*)d_out;

    const int B = in_sizes[0] / HDIM;

    void* fp = nullptr;
    cudaDriverEntryPointQueryResult qr;
    cudaGetDriverEntryPoint("cuTensorMapEncodeTiled", &fp, cudaEnableDefault, &qr);
    EncodeTiledFn encode = (EncodeTiledFn)fp;

    CUtensorMap tmap;
    cuuint64_t dims[2]    = {(cuuint64_t)HDIM, (cuuint64_t)B};
    cuuint64_t strides[1] = {(cuuint64_t)HDIM * 4};
    cuuint32_t box[2]     = {KCHUNK, TILE_ROWS};   // 128 B x 64 rows = 8 KB
    cuuint32_t estr[2]    = {1, 1};
    encode(&tmap, CU_TENSOR_MAP_DATA_TYPE_FLOAT32, 2, (void*)hidden,
           dims, strides, box, estr,
           CU_TENSOR_MAP_INTERLEAVE_NONE, CU_TENSOR_MAP_SWIZZLE_128B,
           CU_TENSOR_MAP_L2_PROMOTION_L2_128B, CU_TENSOR_MAP_FLOAT_OOB_FILL_NONE);

    static bool attr_set = false;
    if (!attr_set) {
        cudaFuncSetAttribute(qreg_tmapipe_kernel,
                             cudaFuncAttributeMaxDynamicSharedMemorySize,
                             DSMEM_BYTES);
        attr_set = true;
    }

    qreg_tmapipe_kernel<<<GRID_SMS, NTHREADS, DSMEM_BYTES>>>(tmap, Wm, bv, out, B);
}

// round 10
// speedup vs baseline: 1.6649x; 1.0541x over previous
#include <cuda_runtime.h>
#include <cstdint>

// QRegulariser: out = mean_b( 1 - prod_q cos^2( (hidden@W.T + b)_q / 2 ) )
// B=65536, H=1024, Q=8. HBM-bound: 256 MB of hidden.
//
// R10: GMEM-SEQUENTIAL streaming. R3-R9 all read 128-512B runs at 4KB stride
// and all pinned DRAM at 60-65% (incl. R9's pure-TMA path) -> DRAM row-buffer
// locality is the limiter. Now each tile = 16 complete rows = 64KB contiguous,
// fetched as 16 x 4KB cp.async.bulk (1D, fully contiguous) into padded smem
// rows (stride 4096+16 -> conflict-free m16n8k8 A-fragment LDS).
//  - double-buffered 64KB tiles, mbarrier expect_tx = 64KB per tile.
//  - 4 consumer warps split K (256 each, 32 tf32 MMA slices), partials
//    reduced via smem, warp 0 does the cos-product epilogue.
//  - producer warp issues the bulk copies (R9-validated handshake).

#define HDIM 1024
#define QDIM 8
#define TILE_ROWS 16
#define ROW_BYTES (HDIM * 4)            // 4096
#define ROW_PAD 16
#define ROW_STRIDE (ROW_BYTES + ROW_PAD) // 4112
#define TILE_BYTES (TILE_ROWS * ROW_BYTES)   // 65536 (tx bytes)
#define TILE_SMEM (TILE_ROWS * ROW_STRIDE)   // 65792
#define NBUF 2
#define NCONS 4
#define NTHREADS 160
#define GRID_SMS 148
#define NSLICES (HDIM / 8)               // 128
#define SLICES_PER_WARP (NSLICES / NCONS) // 32
#define BFRAG_BYTES (NSLICES * 32 * 8)   // 32768
#define DSMEM_BYTES (BFRAG_BYTES + NBUF * TILE_SMEM + 1024)

__device__ double g_partials[GRID_SMS];
__device__ unsigned int g_counter = 0;

__device__ __forceinline__ uint32_t smem_u32(const void* p) {
    uint32_t a;
    asm("{ .reg .u64 t; cvta.to.shared.u64 t, %1; cvt.u32.u64 %0, t; }" : "=r"(a) : "l"(p));
    return a;
}
__device__ __forceinline__ uint32_t elect_one() {
    uint32_t p;
    asm volatile("{ .reg .pred p; elect.sync _|p, 0xFFFFFFFF; selp.b32 %0, 1, 0, p; }" : "=r"(p));
    return p;
}
#define MBARRIER_INIT(a, n) \
    asm volatile("mbarrier.init.shared.b64 [%0], %1;" :: "r"(a), "r"((uint32_t)(n)) : "memory")
#define MBARRIER_EXPECT_TX(a, tx) \
    asm volatile("mbarrier.arrive.expect_tx.shared.b64 _, [%0], %1;" :: "r"(a), "r"((uint32_t)(tx)) : "memory")
#define MBARRIER_ARRIVE(a) \
    asm volatile("mbarrier.arrive.shared.b64 _, [%0];" :: "r"(a) : "memory")
#define MBAR_WAIT(a, par) do {                                              \
    uint32_t _m = (a), _p = (par), _d;                                      \
    asm volatile("{ .reg .pred p; mbarrier.try_wait.parity.acquire.cta.shared::cta.b64 p, [%1], %2;" \
                 " selp.b32 %0, 1, 0, p; }" : "=r"(_d) : "r"(_m), "r"(_p) : "memory");             \
    if (!_d) {                                                              \
        asm volatile("{ .reg .pred P1; WL_%=: mbarrier.try_wait.parity.acquire.cta.shared::cta.b64 P1, [%0], %1, 0x989680;" \
                     " @P1 bra.uni WD_%=; bra.uni WL_%=; WD_%=: }" :: "r"(_m), "r"(_p) : "memory"); \
    } } while (0)
__device__ __forceinline__ void bulk_copy(uint32_t dst, const void* src,
                                          uint32_t bytes, uint32_t mbar) {
    asm volatile("cp.async.bulk.shared::cta.global.mbarrier::complete_tx::bytes "
                 "[%0], [%1], %2, [%3];"
                 :: "r"(dst), "l"(src), "r"(bytes), "r"(mbar) : "memory");
}
// D(16x8) += A(16x8) * B(8x8); tf32 inputs as raw f32 bit patterns.
__device__ __forceinline__ void mma_tf32(float4& d,
                                         uint32_t a0, uint32_t a1, uint32_t a2, uint32_t a3,
                                         uint32_t b0, uint32_t b1) {
    asm volatile(
        "mma.sync.aligned.m16n8k8.row.col.f32.tf32.tf32.f32 "
        "{%0,%1,%2,%3}, {%4,%5,%6,%7}, {%8,%9}, {%0,%1,%2,%3};"
        : "+f"(d.x), "+f"(d.y), "+f"(d.z), "+f"(d.w)
        : "r"(a0), "r"(a1), "r"(a2), "r"(a3), "r"(b0), "r"(b1));
}

__global__ __launch_bounds__(NTHREADS, 1)
void qreg_seq_kernel(const float* __restrict__ hidden,
                     const float* __restrict__ Wm,
                     const float* __restrict__ bv,
                     float* __restrict__ out,
                     int B) {
    extern __shared__ char dsm_raw[];
    __shared__ __align__(8) uint64_t mb_full[NBUF], mb_empty[NBUF];
    __shared__ float4 sPart[NCONS][32];
    __shared__ unsigned int is_last;

    const int tid = threadIdx.x;
    const int warp = tid >> 5, lane = tid & 31;
    const int bid = blockIdx.x;

    // 1024-align dynamic smem.
    const uint32_t raw = smem_u32(dsm_raw);
    const uint32_t base = (raw + 1023u) & ~1023u;
    char* sBf = dsm_raw + (base - raw);             // 32 KB B fragments
    const uint32_t tiles_u = base + BFRAG_BYTES;    // tile buffers
    char* tiles_g = sBf + BFRAG_BYTES;

    // Pack B fragments (R8-validated mapping):
    // slice s, lane l: b0 = W[l/4][8s + l%4], b1 = W[l/4][8s + l%4 + 4].
    for (int i = tid; i < NSLICES * 32; i += NTHREADS) {
        const int s = i >> 5, l = i & 31;
        const int n = l >> 2, k = 8 * s + (l & 3);
        float2 v;
        v.x = Wm[n * HDIM + k];
        v.y = Wm[n * HDIM + k + 4];
        *reinterpret_cast<float2*>(sBf + s * 256 + l * 8) = v;
    }
    if (tid == 0) {
        #pragma unroll
        for (int b = 0; b < NBUF; ++b) {
            MBARRIER_INIT(smem_u32(&mb_full[b]), 1);       // tx completes it
            MBARRIER_INIT(smem_u32(&mb_empty[b]), NCONS);  // 1 arrive/consumer
        }
    }
    __syncthreads();

    const int ntiles = (B + TILE_ROWS - 1) / TILE_ROWS;

    if (warp == NCONS) {
        // ---- Producer: 16 contiguous 4KB bulk copies per tile.
        if (elect_one()) {
            int i = 0;
            for (int t = bid; t < ntiles; t += GRID_SMS, ++i) {
                const int buf = i & 1;
                const uint32_t epar = (((i >> 1) & 1) ^ 1);   // first pass free
                MBAR_WAIT(smem_u32(&mb_empty[buf]), epar);
                const int row0 = t * TILE_ROWS;
                int nv = B - row0; if (nv > TILE_ROWS) nv = TILE_ROWS;
                MBARRIER_EXPECT_TX(smem_u32(&mb_full[buf]),
                                   (uint32_t)nv * ROW_BYTES);
                const uint32_t dst0 = tiles_u + (uint32_t)buf * TILE_SMEM;
                const char* src0 = (const char*)hidden + (size_t)row0 * ROW_BYTES;
                #pragma unroll
                for (int r = 0; r < TILE_ROWS; ++r) {
                    if (r < nv)
                        bulk_copy(dst0 + (uint32_t)r * ROW_STRIDE,
                                  src0 + (size_t)r * ROW_BYTES,
                                  ROW_BYTES, smem_u32(&mb_full[buf]));
                }
            }
        }
    } else {
        // ---- Consumer warp w: K-range [w*256, w*256+256) of every tile.
        const int rl = lane >> 2;           // fragment row 0..7
        const int kl = lane & 3;            // fragment k-lane 0..3
        const float b0v = bv[2 * kl];
        const float b1v = bv[2 * kl + 1];

        double local = 0.0;
        int i = 0;
        for (int t = bid; t < ntiles; t += GRID_SMS, ++i) {
            const int buf = i & 1;
            const uint32_t fpar = (i >> 1) & 1;
            MBAR_WAIT(smem_u32(&mb_full[buf]), fpar);

            const char* Tb = tiles_g + buf * TILE_SMEM;
            // Lane base: row rl (and +8 rows at +8*ROW_STRIDE), element 8s+kl.
            const char* pa = Tb + rl * ROW_STRIDE + kl * 4
                           + warp * (SLICES_PER_WARP * 32);

            float4 acc0 = make_float4(0.f, 0.f, 0.f, 0.f);
            float4 acc1 = make_float4(0.f, 0.f, 0.f, 0.f);
            const char* pb = sBf + (size_t)(warp * SLICES_PER_WARP) * 256 + lane * 8;

            #pragma unroll 8
            for (int j = 0; j < SLICES_PER_WARP; ++j) {
                const char* p = pa + j * 32;
                const uint32_t a0 = *reinterpret_cast<const uint32_t*>(p);
                const uint32_t a1 = *reinterpret_cast<const uint32_t*>(p + 8 * ROW_STRIDE);
                const uint32_t a2 = *reinterpret_cast<const uint32_t*>(p + 16);
                const uint32_t a3 = *reinterpret_cast<const uint32_t*>(p + 8 * ROW_STRIDE + 16);
                const float2 bf = *reinterpret_cast<const float2*>(pb + j * 256);
                float4& acc = (j & 1) ? acc1 : acc0;
                mma_tf32(acc, a0, a1, a2, a3,
                         __float_as_uint(bf.x), __float_as_uint(bf.y));
            }
            // Reads done -> free the buffer slot.
            if (elect_one()) MBARRIER_ARRIVE(smem_u32(&mb_empty[buf]));

            float4 acc;
            acc.x = acc0.x + acc1.x; acc.y = acc0.y + acc1.y;
            acc.z = acc0.z + acc1.z; acc.w = acc0.w + acc1.w;
            sPart[warp][lane] = acc;
            asm volatile("bar.sync 1, 128;" ::: "memory");

            if (warp == 0) {
                float4 a = sPart[0][lane];
                #pragma unroll
                for (int w = 1; w < NCONS; ++w) {
                    const float4 b = sPart[w][lane];
                    a.x += b.x; a.y += b.y; a.z += b.z; a.w += b.w;
                }
                const float tA0 = a.x + b0v, tA1 = a.y + b1v;
                const float tB0 = a.z + b0v, tB1 = a.w + b1v;
                float pA = 0.25f * (1.0f + __cosf(tA0)) * (1.0f + __cosf(tA1));
                float pB = 0.25f * (1.0f + __cosf(tB0)) * (1.0f + __cosf(tB1));
                #pragma unroll
                for (int d = 1; d <= 2; d <<= 1) {
                    pA *= __shfl_xor_sync(0xffffffffu, pA, d);
                    pB *= __shfl_xor_sync(0xffffffffu, pB, d);
                }
                const int rowA = t * TILE_ROWS + rl;
                const int rowB = rowA + 8;
                float sv = ((rowA < B) ? (1.0f - pA) : 0.0f)
                         + ((rowB < B) ? (1.0f - pB) : 0.0f);
                #pragma unroll
                for (int d = 1; d <= 16; d <<= 1)
                    sv += __shfl_xor_sync(0xffffffffu, sv, d);
                local += (double)sv * 0.25;   // quad replication
            }
            asm volatile("bar.sync 1, 128;" ::: "memory");  // protect sPart
        }
        // keep `local` (only warp 0's is the answer)
        if (warp == 0 && lane == 0) sPart[0][0].x = 0.f;  // no-op keepalive
        if (warp == 0) {
            // stash in shared for the tail (lane0 value is the block sum)
        }
        if (lane == 0 && warp == 0) *(double*)&sPart[1][0] = local;
    }
    __syncthreads();

    if (tid == 0) {
        const double ssum = *(double*)&sPart[1][0];
        g_partials[bid] = ssum;
        __threadfence();
        const unsigned int prev = atomicAdd(&g_counter, 1u);
        is_last = (prev == gridDim.x - 1) ? 1u : 0u;
    }
    __syncthreads();

    if (is_last) {
        __threadfence();
        const volatile double* vp = g_partials;
        double ssum = 0.0;
        for (int i = tid; i < (int)gridDim.x; i += NTHREADS) ssum += vp[i];
        #pragma unroll
        for (int d = 16; d > 0; d >>= 1)
            ssum += __shfl_down_sync(0xffffffffu, ssum, d);
        __shared__ double fin[5];
        if (lane == 0) fin[warp] = ssum;
        __syncthreads();
        if (tid == 0) {
            double tt = 0.0;
            #pragma unroll
            for (int w = 0; w < 5; ++w) tt += fin[w];
            out[0] = (float)(tt / (double)B);
            g_counter = 0;   // reset for graph replay
        }
    }
}

extern "C" void kernel_launch(void* const* d_in, const int* in_sizes, int n_in,
                              void* d_out, int out_size) {
    const float* hidden = (const float*)d_in[0];   // [B, H] f32
    const float* Wm     = (const float*)d_in[1];   // [Q, H] f32
    const float* bv     = (const float*)d_in[2];   // [Q]    f32
    float* out = (float*)d_out;

    const int B = in_sizes[0] / HDIM;

    static bool attr_set = false;
    if (!attr_set) {
        cudaFuncSetAttribute(qreg_seq_kernel,
                             cudaFuncAttributeMaxDynamicSharedMemorySize,
                             DSMEM_BYTES);
        attr_set = true;
    }

    qreg_seq_kernel<<<GRID_SMS, NTHREADS, DSMEM_BYTES>>>(hidden, Wm, bv, out, B);
}

// round 12
// speedup vs baseline: 1.7366x; 1.0430x over previous
#include <cuda_runtime.h>
#include <cstdint>

// QRegulariser: out = mean_b( 1 - prod_q cos^2( (hidden@W.T + b)_q / 2 ) )
// B=65536, H=1024, Q=8. Pure DRAM-duty-cycle problem (256 MB of hidden).
//
// R12 = R11 (NBUF=3 + contiguous per-SM ranges) made to FIT:
//  R11 failed launch: 231KB dynamic + 2.2KB static > 227KB smem cap.
//  - B fragments moved smem -> registers (each consumer warp only needs its
//    own 32 slices = 64 f32 regs/thread, loaded once from gmem W).
//  - dynamic smem = 3 x 65792 + 1024 = 198400 (fits).
//  - NBUF=3: producer keeps 2 tiles in flight while 1 is consumed.
//  - balanced contiguous tile ranges: one unbroken ~1.8MB stream per SM.

#define HDIM 1024
#define QDIM 8
#define TILE_ROWS 16
#define ROW_BYTES (HDIM * 4)             // 4096
#define ROW_PAD 16
#define ROW_STRIDE (ROW_BYTES + ROW_PAD) // 4112
#define TILE_SMEM (TILE_ROWS * ROW_STRIDE)   // 65792
#define NBUF 3
#define NCONS 4
#define NTHREADS 160
#define GRID_SMS 148
#define SLICES_PER_WARP 32               // 128 k-slices / 4 warps
#define DSMEM_BYTES (NBUF * TILE_SMEM + 1024)  // 198400

__device__ double g_partials[GRID_SMS];
__device__ unsigned int g_counter = 0;

__device__ __forceinline__ uint32_t smem_u32(const void* p) {
    uint32_t a;
    asm("{ .reg .u64 t; cvta.to.shared.u64 t, %1; cvt.u32.u64 %0, t; }" : "=r"(a) : "l"(p));
    return a;
}
__device__ __forceinline__ uint32_t elect_one() {
    uint32_t p;
    asm volatile("{ .reg .pred p; elect.sync _|p, 0xFFFFFFFF; selp.b32 %0, 1, 0, p; }" : "=r"(p));
    return p;
}
#define MBARRIER_INIT(a, n) \
    asm volatile("mbarrier.init.shared.b64 [%0], %1;" :: "r"(a), "r"((uint32_t)(n)) : "memory")
#define MBARRIER_EXPECT_TX(a, tx) \
    asm volatile("mbarrier.arrive.expect_tx.shared.b64 _, [%0], %1;" :: "r"(a), "r"((uint32_t)(tx)) : "memory")
#define MBARRIER_ARRIVE(a) \
    asm volatile("mbarrier.arrive.shared.b64 _, [%0];" :: "r"(a) : "memory")
#define MBAR_WAIT(a, par) do {                                              \
    uint32_t _m = (a), _p = (par), _d;                                      \
    asm volatile("{ .reg .pred p; mbarrier.try_wait.parity.acquire.cta.shared::cta.b64 p, [%1], %2;" \
                 " selp.b32 %0, 1, 0, p; }" : "=r"(_d) : "r"(_m), "r"(_p) : "memory");             \
    if (!_d) {                                                              \
        asm volatile("{ .reg .pred P1; WL_%=: mbarrier.try_wait.parity.acquire.cta.shared::cta.b64 P1, [%0], %1, 0x989680;" \
                     " @P1 bra.uni WD_%=; bra.uni WL_%=; WD_%=: }" :: "r"(_m), "r"(_p) : "memory"); \
    } } while (0)
__device__ __forceinline__ void bulk_copy(uint32_t dst, const void* src,
                                          uint32_t bytes, uint32_t mbar) {
    asm volatile("cp.async.bulk.shared::cta.global.mbarrier::complete_tx::bytes "
                 "[%0], [%1], %2, [%3];"
                 :: "r"(dst), "l"(src), "r"(bytes), "r"(mbar) : "memory");
}
// D(16x8) += A(16x8) * B(8x8); tf32 inputs as raw f32 bit patterns.
__device__ __forceinline__ void mma_tf32(float4& d,
                                         uint32_t a0, uint32_t a1, uint32_t a2, uint32_t a3,
                                         uint32_t b0, uint32_t b1) {
    asm volatile(
        "mma.sync.aligned.m16n8k8.row.col.f32.tf32.tf32.f32 "
        "{%0,%1,%2,%3}, {%4,%5,%6,%7}, {%8,%9}, {%0,%1,%2,%3};"
        : "+f"(d.x), "+f"(d.y), "+f"(d.z), "+f"(d.w)
        : "r"(a0), "r"(a1), "r"(a2), "r"(a3), "r"(b0), "r"(b1));
}

__global__ __launch_bounds__(NTHREADS, 1)
void qreg_seq3_kernel(const float* __restrict__ hidden,
                      const float* __restrict__ Wm,
                      const float* __restrict__ bv,
                      float* __restrict__ out,
                      int B) {
    extern __shared__ char dsm_raw[];
    __shared__ __align__(8) uint64_t mb_full[NBUF], mb_empty[NBUF];
    __shared__ float4 sPart[NCONS][32];
    __shared__ double block_sum;
    __shared__ unsigned int is_last;

    const int tid = threadIdx.x;
    const int warp = tid >> 5, lane = tid & 31;
    const int bid = blockIdx.x;

    // 1024-align dynamic smem.
    const uint32_t raw = smem_u32(dsm_raw);
    const uint32_t base = (raw + 1023u) & ~1023u;
    const uint32_t tiles_u = base;                 // 3 tile buffers
    char* tiles_g = dsm_raw + (base - raw);

    if (tid == 0) {
        #pragma unroll
        for (int b = 0; b < NBUF; ++b) {
            MBARRIER_INIT(smem_u32(&mb_full[b]), 1);       // tx completes it
            MBARRIER_INIT(smem_u32(&mb_empty[b]), NCONS);  // 1 arrive/consumer
        }
        block_sum = 0.0;
    }
    __syncthreads();

    // Balanced contiguous partition: first `rem` blocks get q+1 tiles.
    const int ntiles = (B + TILE_ROWS - 1) / TILE_ROWS;
    const int q = ntiles / GRID_SMS, rem = ntiles - q * GRID_SMS;
    const int t0 = bid * q + (bid < rem ? bid : rem);
    const int nmy = q + (bid < rem ? 1 : 0);

    if (warp == NCONS) {
        // ---- Producer: 16 contiguous 4KB bulk copies per tile; 3-deep ring.
        if (elect_one()) {
            for (int i = 0; i < nmy; ++i) {
                const int buf = i % NBUF;
                const uint32_t epar = (((i / NBUF) & 1) ^ 1);  // first pass free
                MBAR_WAIT(smem_u32(&mb_empty[buf]), epar);
                const int row0 = (t0 + i) * TILE_ROWS;
                int nv = B - row0; if (nv > TILE_ROWS) nv = TILE_ROWS;
                MBARRIER_EXPECT_TX(smem_u32(&mb_full[buf]),
                                   (uint32_t)nv * ROW_BYTES);
                const uint32_t dst0 = tiles_u + (uint32_t)buf * TILE_SMEM;
                const char* src0 = (const char*)hidden + (size_t)row0 * ROW_BYTES;
                #pragma unroll
                for (int r = 0; r < TILE_ROWS; ++r) {
                    if (r < nv)
                        bulk_copy(dst0 + (uint32_t)r * ROW_STRIDE,
                                  src0 + (size_t)r * ROW_BYTES,
                                  ROW_BYTES, smem_u32(&mb_full[buf]));
                }
            }
        }
    } else {
        // ---- Consumer warp w: K-range [w*256, (w+1)*256) of every tile.
        const int rl = lane >> 2;           // fragment row 0..7
        const int kl = lane & 3;            // fragment k-lane 0..3
        const float b0v = bv[2 * kl];
        const float b1v = bv[2 * kl + 1];

        // B fragments in registers: slice j (global slice s = warp*32 + j):
        // b0 = W[lane/4][8s + lane%4], b1 = W[lane/4][8s + lane%4 + 4].
        uint32_t bf0[SLICES_PER_WARP], bf1[SLICES_PER_WARP];
        {
            const int n = lane >> 2;
            const float* wr = Wm + n * HDIM + (warp * SLICES_PER_WARP) * 8 + kl;
            #pragma unroll
            for (int j = 0; j < SLICES_PER_WARP; ++j) {
                bf0[j] = __float_as_uint(wr[j * 8]);
                bf1[j] = __float_as_uint(wr[j * 8 + 4]);
            }
        }

        double local = 0.0;
        for (int i = 0; i < nmy; ++i) {
            const int buf = i % NBUF;
            const uint32_t fpar = (i / NBUF) & 1;
            MBAR_WAIT(smem_u32(&mb_full[buf]), fpar);

            const char* Tb = tiles_g + buf * TILE_SMEM;
            const char* pa = Tb + rl * ROW_STRIDE + kl * 4
                           + warp * (SLICES_PER_WARP * 32);

            float4 acc0 = make_float4(0.f, 0.f, 0.f, 0.f);
            float4 acc1 = make_float4(0.f, 0.f, 0.f, 0.f);

            #pragma unroll
            for (int j = 0; j < SLICES_PER_WARP; ++j) {
                const char* p = pa + j * 32;
                const uint32_t a0 = *reinterpret_cast<const uint32_t*>(p);
                const uint32_t a1 = *reinterpret_cast<const uint32_t*>(p + 8 * ROW_STRIDE);
                const uint32_t a2 = *reinterpret_cast<const uint32_t*>(p + 16);
                const uint32_t a3 = *reinterpret_cast<const uint32_t*>(p + 8 * ROW_STRIDE + 16);
                float4& acc = (j & 1) ? acc1 : acc0;
                mma_tf32(acc, a0, a1, a2, a3, bf0[j], bf1[j]);
            }
            // Reads done -> free the buffer slot.
            if (elect_one()) MBARRIER_ARRIVE(smem_u32(&mb_empty[buf]));

            float4 acc;
            acc.x = acc0.x + acc1.x; acc.y = acc0.y + acc1.y;
            acc.z = acc0.z + acc1.z; acc.w = acc0.w + acc1.w;
            sPart[warp][lane] = acc;
            asm volatile("bar.sync 1, 128;" ::: "memory");

            if (warp == 0) {
                float4 a = sPart[0][lane];
                #pragma unroll
                for (int w = 1; w < NCONS; ++w) {
                    const float4 b = sPart[w][lane];
                    a.x += b.x; a.y += b.y; a.z += b.z; a.w += b.w;
                }
                const float tA0 = a.x + b0v, tA1 = a.y + b1v;
                const float tB0 = a.z + b0v, tB1 = a.w + b1v;
                float pA = 0.25f * (1.0f + __cosf(tA0)) * (1.0f + __cosf(tA1));
                float pB = 0.25f * (1.0f + __cosf(tB0)) * (1.0f + __cosf(tB1));
                #pragma unroll
                for (int d = 1; d <= 2; d <<= 1) {
                    pA *= __shfl_xor_sync(0xffffffffu, pA, d);
                    pB *= __shfl_xor_sync(0xffffffffu, pB, d);
                }
                const int rowA = (t0 + i) * TILE_ROWS + rl;
                const int rowB = rowA + 8;
                float sv = ((rowA < B) ? (1.0f - pA) : 0.0f)
                         + ((rowB < B) ? (1.0f - pB) : 0.0f);
                #pragma unroll
                for (int d = 1; d <= 16; d <<= 1)
                    sv += __shfl_xor_sync(0xffffffffu, sv, d);
                local += (double)sv * 0.25;   // quad replication
            }
            asm volatile("bar.sync 1, 128;" ::: "memory");  // protect sPart
        }
        if (warp == 0 && lane == 0) block_sum = local;
    }
    __syncthreads();

    if (tid == 0) {
        g_partials[bid] = block_sum;
        __threadfence();
        const unsigned int prev = atomicAdd(&g_counter, 1u);
        is_last = (prev == gridDim.x - 1) ? 1u : 0u;
    }
    __syncthreads();

    if (is_last) {
        __threadfence();
        const volatile double* vp = g_partials;
        double ssum = 0.0;
        for (int i = tid; i < (int)gridDim.x; i += NTHREADS) ssum += vp[i];
        #pragma unroll
        for (int d = 16; d > 0; d >>= 1)
            ssum += __shfl_down_sync(0xffffffffu, ssum, d);
        __shared__ double fin[5];
        if (lane == 0) fin[warp] = ssum;
        __syncthreads();
        if (tid == 0) {
            double tt = 0.0;
            #pragma unroll
            for (int w = 0; w < 5; ++w) tt += fin[w];
            out[0] = (float)(tt / (double)B);
            g_counter = 0;   // reset for graph replay
        }
    }
}

extern "C" void kernel_launch(void* const* d_in, const int* in_sizes, int n_in,
                              void* d_out, int out_size) {
    const float* hidden = (const float*)d_in[0];   // [B, H] f32
    const float* Wm     = (const float*)d_in[1];   // [Q, H] f32
    const float* bv     = (const float*)d_in[2];   // [Q]    f32
    float* out = (float*)d_out;

    const int B = in_sizes[0] / HDIM;

    static bool attr_set = false;
    if (!attr_set) {
        cudaFuncSetAttribute(qreg_seq3_kernel,
                             cudaFuncAttributeMaxDynamicSharedMemorySize,
                             DSMEM_BYTES);
        attr_set = true;
    }

    qreg_seq3_kernel<<<GRID_SMS, NTHREADS, DSMEM_BYTES>>>(hidden, Wm, bv, out, B);
}

// round 13
// speedup vs baseline: 1.7377x; 1.0007x over previous
#include <cuda_runtime.h>
#include <cstdint>

// QRegulariser: out = mean_b( 1 - prod_q cos^2( (hidden@W.T + b)_q / 2 ) )
// B=65536, H=1024, Q=8. DRAM-duty problem (256 MB of hidden).
//
// R13 vs R12 (47.6us, DRAM 71%): consumers were pacing the ring (~1600-2000cyc
// critical path/tile vs 1770 needed at DRAM=100%). Changes:
//  - 8 consumer warps (K-split 128 els each): MMA chain 900 -> ~250 cyc.
//  - epilogue rotated across warps (tile i -> warp i%8) and taken OFF the
//    critical path: sPart in 3 rotating slots, ONE bar.sync per tile; the
//    epilogue warp lags while others advance.
//  - producer/ring unchanged: NBUF=3 x 64KB tiles, 16x4KB cp.async.bulk,
//    contiguous per-SM tile ranges.

#define HDIM 1024
#define QDIM 8
#define TILE_ROWS 16
#define ROW_BYTES (HDIM * 4)             // 4096
#define ROW_PAD 16
#define ROW_STRIDE (ROW_BYTES + ROW_PAD) // 4112
#define TILE_SMEM (TILE_ROWS * ROW_STRIDE)   // 65792
#define NBUF 3
#define NCONS 8
#define NTHREADS ((NCONS + 1) * 32)      // 288
#define GRID_SMS 148
#define SLICES_PER_WARP 16               // 128 k-slices / 8 warps
#define DSMEM_BYTES (NBUF * TILE_SMEM + 1024)  // 198400

__device__ double g_partials[GRID_SMS];
__device__ unsigned int g_counter = 0;

__device__ __forceinline__ uint32_t smem_u32(const void* p) {
    uint32_t a;
    asm("{ .reg .u64 t; cvta.to.shared.u64 t, %1; cvt.u32.u64 %0, t; }" : "=r"(a) : "l"(p));
    return a;
}
__device__ __forceinline__ uint32_t elect_one() {
    uint32_t p;
    asm volatile("{ .reg .pred p; elect.sync _|p, 0xFFFFFFFF; selp.b32 %0, 1, 0, p; }" : "=r"(p));
    return p;
}
#define MBARRIER_INIT(a, n) \
    asm volatile("mbarrier.init.shared.b64 [%0], %1;" :: "r"(a), "r"((uint32_t)(n)) : "memory")
#define MBARRIER_EXPECT_TX(a, tx) \
    asm volatile("mbarrier.arrive.expect_tx.shared.b64 _, [%0], %1;" :: "r"(a), "r"((uint32_t)(tx)) : "memory")
#define MBARRIER_ARRIVE(a) \
    asm volatile("mbarrier.arrive.shared.b64 _, [%0];" :: "r"(a) : "memory")
#define MBAR_WAIT(a, par) do {                                              \
    uint32_t _m = (a), _p = (par), _d;                                      \
    asm volatile("{ .reg .pred p; mbarrier.try_wait.parity.acquire.cta.shared::cta.b64 p, [%1], %2;" \
                 " selp.b32 %0, 1, 0, p; }" : "=r"(_d) : "r"(_m), "r"(_p) : "memory");             \
    if (!_d) {                                                              \
        asm volatile("{ .reg .pred P1; WL_%=: mbarrier.try_wait.parity.acquire.cta.shared::cta.b64 P1, [%0], %1, 0x989680;" \
                     " @P1 bra.uni WD_%=; bra.uni WL_%=; WD_%=: }" :: "r"(_m), "r"(_p) : "memory"); \
    } } while (0)
__device__ __forceinline__ void bulk_copy(uint32_t dst, const void* src,
                                          uint32_t bytes, uint32_t mbar) {
    asm volatile("cp.async.bulk.shared::cta.global.mbarrier::complete_tx::bytes "
                 "[%0], [%1], %2, [%3];"
                 :: "r"(dst), "l"(src), "r"(bytes), "r"(mbar) : "memory");
}
// D(16x8) += A(16x8) * B(8x8); tf32 inputs as raw f32 bit patterns.
__device__ __forceinline__ void mma_tf32(float4& d,
                                         uint32_t a0, uint32_t a1, uint32_t a2, uint32_t a3,
                                         uint32_t b0, uint32_t b1) {
    asm volatile(
        "mma.sync.aligned.m16n8k8.row.col.f32.tf32.tf32.f32 "
        "{%0,%1,%2,%3}, {%4,%5,%6,%7}, {%8,%9}, {%0,%1,%2,%3};"
        : "+f"(d.x), "+f"(d.y), "+f"(d.z), "+f"(d.w)
        : "r"(a0), "r"(a1), "r"(a2), "r"(a3), "r"(b0), "r"(b1));
}

__global__ __launch_bounds__(NTHREADS, 1)
void qreg_r13_kernel(const float* __restrict__ hidden,
                     const float* __restrict__ Wm,
                     const float* __restrict__ bv,
                     float* __restrict__ out,
                     int B) {
    extern __shared__ char dsm_raw[];
    __shared__ __align__(8) uint64_t mb_full[NBUF], mb_empty[NBUF];
    __shared__ float4 sPart[3][NCONS][32];        // 3 rotating slots
    __shared__ double warp_locals[NCONS];
    __shared__ unsigned int is_last;

    const int tid = threadIdx.x;
    const int warp = tid >> 5, lane = tid & 31;
    const int bid = blockIdx.x;

    // 1024-align dynamic smem.
    const uint32_t raw = smem_u32(dsm_raw);
    const uint32_t base = (raw + 1023u) & ~1023u;
    const uint32_t tiles_u = base;                 // 3 tile buffers
    char* tiles_g = dsm_raw + (base - raw);

    if (tid == 0) {
        #pragma unroll
        for (int b = 0; b < NBUF; ++b) {
            MBARRIER_INIT(smem_u32(&mb_full[b]), 1);       // tx completes it
            MBARRIER_INIT(smem_u32(&mb_empty[b]), NCONS);  // 1 arrive/consumer
        }
    }
    if (tid < NCONS) warp_locals[tid] = 0.0;
    __syncthreads();

    // Balanced contiguous partition: first `rem` blocks get q+1 tiles.
    const int ntiles = (B + TILE_ROWS - 1) / TILE_ROWS;
    const int q = ntiles / GRID_SMS, rem = ntiles - q * GRID_SMS;
    const int t0 = bid * q + (bid < rem ? bid : rem);
    const int nmy = q + (bid < rem ? 1 : 0);

    if (warp == NCONS) {
        // ---- Producer: 16 contiguous 4KB bulk copies per tile; 3-deep ring.
        if (elect_one()) {
            for (int i = 0; i < nmy; ++i) {
                const int buf = i % NBUF;
                const uint32_t epar = (((i / NBUF) & 1) ^ 1);  // first pass free
                MBAR_WAIT(smem_u32(&mb_empty[buf]), epar);
                const int row0 = (t0 + i) * TILE_ROWS;
                int nv = B - row0; if (nv > TILE_ROWS) nv = TILE_ROWS;
                MBARRIER_EXPECT_TX(smem_u32(&mb_full[buf]),
                                   (uint32_t)nv * ROW_BYTES);
                const uint32_t dst0 = tiles_u + (uint32_t)buf * TILE_SMEM;
                const char* src0 = (const char*)hidden + (size_t)row0 * ROW_BYTES;
                #pragma unroll
                for (int r = 0; r < TILE_ROWS; ++r) {
                    if (r < nv)
                        bulk_copy(dst0 + (uint32_t)r * ROW_STRIDE,
                                  src0 + (size_t)r * ROW_BYTES,
                                  ROW_BYTES, smem_u32(&mb_full[buf]));
                }
            }
        }
    } else {
        // ---- Consumer warp w: K-range [w*128, (w+1)*128) of every tile.
        const int rl = lane >> 2;           // fragment row 0..7
        const int kl = lane & 3;            // fragment k-lane 0..3
        const float b0v = bv[2 * kl];
        const float b1v = bv[2 * kl + 1];

        // B fragments in registers: slice j (global slice s = warp*16 + j):
        // b0 = W[lane/4][8s + lane%4], b1 = W[lane/4][8s + lane%4 + 4].
        uint32_t bf0[SLICES_PER_WARP], bf1[SLICES_PER_WARP];
        {
            const int n = lane >> 2;
            const float* wr = Wm + n * HDIM + (warp * SLICES_PER_WARP) * 8 + kl;
            #pragma unroll
            for (int j = 0; j < SLICES_PER_WARP; ++j) {
                bf0[j] = __float_as_uint(wr[j * 8]);
                bf1[j] = __float_as_uint(wr[j * 8 + 4]);
            }
        }

        double local = 0.0;
        for (int i = 0; i < nmy; ++i) {
            const int buf = i % NBUF;
            const uint32_t fpar = (i / NBUF) & 1;
            MBAR_WAIT(smem_u32(&mb_full[buf]), fpar);

            const char* Tb = tiles_g + buf * TILE_SMEM;
            const char* pa = Tb + rl * ROW_STRIDE + kl * 4
                           + warp * (SLICES_PER_WARP * 32);

            float4 acc0 = make_float4(0.f, 0.f, 0.f, 0.f);
            float4 acc1 = make_float4(0.f, 0.f, 0.f, 0.f);

            #pragma unroll
            for (int j = 0; j < SLICES_PER_WARP; ++j) {
                const char* p = pa + j * 32;
                const uint32_t a0 = *reinterpret_cast<const uint32_t*>(p);
                const uint32_t a1 = *reinterpret_cast<const uint32_t*>(p + 8 * ROW_STRIDE);
                const uint32_t a2 = *reinterpret_cast<const uint32_t*>(p + 16);
                const uint32_t a3 = *reinterpret_cast<const uint32_t*>(p + 8 * ROW_STRIDE + 16);
                float4& acc = (j & 1) ? acc1 : acc0;
                mma_tf32(acc, a0, a1, a2, a3, bf0[j], bf1[j]);
            }
            // Reads done -> free the buffer slot for the producer.
            if (elect_one()) MBARRIER_ARRIVE(smem_u32(&mb_empty[buf]));

            const int ps = i % 3;           // sPart rotating slot
            float4 acc;
            acc.x = acc0.x + acc1.x; acc.y = acc0.y + acc1.y;
            acc.z = acc0.z + acc1.z; acc.w = acc0.w + acc1.w;
            sPart[ps][warp][lane] = acc;
            // One consumer-scope barrier: all partials for tile i stored.
            asm volatile("bar.sync 1, %0;" :: "n"(NCONS * 32) : "memory");

            // Rotated epilogue: warp (i%8) handles tile i off-critical-path.
            // Slot ps is not rewritten until tile i+3 (>= 2 cadences away).
            if (warp == (i & 7)) {
                float4 a = sPart[ps][0][lane];
                #pragma unroll
                for (int w = 1; w < NCONS; ++w) {
                    const float4 b = sPart[ps][w][lane];
                    a.x += b.x; a.y += b.y; a.z += b.z; a.w += b.w;
                }
                const float tA0 = a.x + b0v, tA1 = a.y + b1v;
                const float tB0 = a.z + b0v, tB1 = a.w + b1v;
                float pA = 0.25f * (1.0f + __cosf(tA0)) * (1.0f + __cosf(tA1));
                float pB = 0.25f * (1.0f + __cosf(tB0)) * (1.0f + __cosf(tB1));
                #pragma unroll
                for (int d = 1; d <= 2; d <<= 1) {
                    pA *= __shfl_xor_sync(0xffffffffu, pA, d);
                    pB *= __shfl_xor_sync(0xffffffffu, pB, d);
                }
                const int rowA = (t0 + i) * TILE_ROWS + rl;
                const int rowB = rowA + 8;
                float sv = ((rowA < B) ? (1.0f - pA) : 0.0f)
                         + ((rowB < B) ? (1.0f - pB) : 0.0f);
                #pragma unroll
                for (int d = 1; d <= 16; d <<= 1)
                    sv += __shfl_xor_sync(0xffffffffu, sv, d);
                local += (double)sv * 0.25;   // quad replication
            }
        }
        if (lane == 0) warp_locals[warp] = local;
    }
    __syncthreads();

    if (tid == 0) {
        double bsum = 0.0;
        #pragma unroll
        for (int w = 0; w < NCONS; ++w) bsum += warp_locals[w];
        g_partials[bid] = bsum;
        __threadfence();
        const unsigned int prev = atomicAdd(&g_counter, 1u);
        is_last = (prev == gridDim.x - 1) ? 1u : 0u;
    }
    __syncthreads();

    if (is_last) {
        __threadfence();
        const volatile double* vp = g_partials;
        double ssum = 0.0;
        for (int i = tid; i < (int)gridDim.x; i += NTHREADS) ssum += vp[i];
        #pragma unroll
        for (int d = 16; d > 0; d >>= 1)
            ssum += __shfl_down_sync(0xffffffffu, ssum, d);
        __shared__ double fin[NCONS + 1];
        if (lane == 0) fin[warp] = ssum;
        __syncthreads();
        if (tid == 0) {
            double tt = 0.0;
            #pragma unroll
            for (int w = 0; w < NCONS + 1; ++w) tt += fin[w];
            out[0] = (float)(tt / (double)B);
            g_counter = 0;   // reset for graph replay
        }
    }
}

extern "C" void kernel_launch(void* const* d_in, const int* in_sizes, int n_in,
                              void* d_out, int out_size) {
    const float* hidden = (const float*)d_in[0];   // [B, H] f32
    const float* Wm     = (const float*)d_in[1];   // [Q, H] f32
    const float* bv     = (const float*)d_in[2];   // [Q]    f32
    float* out = (float*)d_out;

    const int B = in_sizes[0] / HDIM;

    static bool attr_set = false;
    if (!attr_set) {
        cudaFuncSetAttribute(qreg_r13_kernel,
                             cudaFuncAttributeMaxDynamicSharedMemorySize,
                             DSMEM_BYTES);
        attr_set = true;
    }

    qreg_r13_kernel<<<GRID_SMS, NTHREADS, DSMEM_BYTES>>>(hidden, Wm, bv, out, B);
}